// round 1
// baseline (speedup 1.0000x reference)
#include <cuda_runtime.h>
#include <cub/cub.cuh>
#include <math.h>

// Problem constants
#define WINDOW 40
#define E 8
#define FDIM 64
#define TDIM 64
#define KERNEL 5
#define IN_CH 144          // F + 10*E
#define LIN_IN 36          // WINDOW + 1 - KERNEL
#define NCOL 320           // WINDOW * E rank columns
#define NMAX 8000

// Scratch (device globals — no allocation allowed)
__device__ float g_cols[NCOL * NMAX];          // [col][n]  col-major gather of last window
__device__ float g_rank[(size_t)NMAX * NCOL];  // [n][col]  rank/N, coalesced for main kernel

// ---------------------------------------------------------------------------
// Kernel 1: gather x[:, 24+t, 0:8] -> g_cols[(t*8+f)][n], one sector per (n,row)
// ---------------------------------------------------------------------------
__global__ void gather_kernel(const float* __restrict__ x, int N) {
    __shared__ float tile[256][9];   // pad 9 -> conflict-free both phases
    const int t  = blockIdx.y;
    const int n0 = blockIdx.x * 256;
    const int tid = threadIdx.x;
    const int n = n0 + tid;
    if (n < N) {
        const float4* p = (const float4*)(x + (size_t)n * (TDIM * FDIM) + (24 + t) * FDIM);
        float4 a = p[0], b = p[1];
        tile[tid][0] = a.x; tile[tid][1] = a.y; tile[tid][2] = a.z; tile[tid][3] = a.w;
        tile[tid][4] = b.x; tile[tid][5] = b.y; tile[tid][6] = b.z; tile[tid][7] = b.w;
    }
    __syncthreads();
    #pragma unroll
    for (int idx = tid; idx < 8 * 256; idx += 256) {
        int f = idx >> 8, s = idx & 255;
        int nn = n0 + s;
        if (nn < N) g_cols[(size_t)(t * 8 + f) * N + nn] = tile[s][f];
    }
}

// ---------------------------------------------------------------------------
// Kernel 2: stable descending rank of each column (== argsort(argsort(-last)))
// ---------------------------------------------------------------------------
#define RT 512
#define RI 16   // 512*16 = 8192 >= 8000

__global__ __launch_bounds__(RT) void rank_kernel(int N) {
    typedef cub::BlockRadixSort<unsigned int, RT, RI, int> Sorter;
    __shared__ typename Sorter::TempStorage temp;
    const int c = blockIdx.x;
    const int tid = threadIdx.x;
    unsigned int keys[RI];
    int          vals[RI];
    #pragma unroll
    for (int j = 0; j < RI; ++j) {
        int p = tid * RI + j;
        if (p < N) {
            unsigned int u = __float_as_uint(g_cols[(size_t)c * N + p]);
            // ascending-monotone transform, then invert for descending
            unsigned int mono = u ^ ((u >> 31) ? 0xFFFFFFFFu : 0x80000000u);
            keys[j] = ~mono;
            vals[j] = p;
        } else {
            keys[j] = 0xFFFFFFFFu;   // sorts last (no NaNs in input)
            vals[j] = 0x7FFFFFFF;
        }
    }
    Sorter(temp).Sort(keys, vals);   // stable radix sort, blocked arrangement
    const float inv = 1.0f / (float)N;
    #pragma unroll
    for (int j = 0; j < RI; ++j) {
        int pos = tid * RI + j;      // position in descending order
        int n = vals[j];
        if (n < N) g_rank[(size_t)n * NCOL + c] = (float)pos * inv;
    }
}

// ---------------------------------------------------------------------------
// Kernel 3: per-sample stats + channel-127 conv + leaky + linear
// ---------------------------------------------------------------------------
__global__ __launch_bounds__(320) void main_kernel(
    const float* __restrict__ x, const float* __restrict__ conv_w,
    const float* __restrict__ conv_b, const float* __restrict__ lin_w,
    const float* __restrict__ lin_b, float* __restrict__ out, int N)
{
    __shared__ float xe[59 * 8];        // rows 5..63 of first 8 features
    __shared__ float xc[WINDOW * IN_CH];// assembled conv input [40][144]
    __shared__ float ws[IN_CH * KERNEL];// conv_w[127]
    __shared__ float lw[LIN_IN];
    __shared__ float red;

    const int n   = blockIdx.x;
    const int tid = threadIdx.x;
    const float* xn = x + (size_t)n * (TDIM * FDIM);

    // ---- phase 1: loads ----
    for (int i = tid; i < IN_CH * KERNEL; i += 320) ws[i] = conv_w[127 * IN_CH * KERNEL + i];
    if (tid < LIN_IN) lw[tid] = lin_w[tid];
    if (tid == 0) red = 0.0f;

    for (int i = tid; i < 59 * 8; i += 320) {
        int r = i >> 3, f = i & 7;
        xe[i] = xn[(5 + r) * FDIM + f];
    }
    // raw channels: x[n, 24:64, 0:64] is 2560 contiguous floats
    {
        const float4* src = (const float4*)(xn + 24 * FDIM);
        for (int q = tid; q < 640; q += 320) {
            float4 v = src[q];
            int l = q * 4;
            int t = l >> 6, i = l & 63;
            *(float4*)&xc[t * IN_CH + i] = v;
        }
    }
    // rank (coalesced): same rank feeds week slot (80..87) and month slot (120..127)
    {
        float r = g_rank[(size_t)n * NCOL + tid];
        int t = tid >> 3, f = tid & 7;
        xc[t * IN_CH + 80 + f]  = r;
        xc[t * IN_CH + 120 + f] = r;
    }
    __syncthreads();

    // ---- phase 2: sliding-window stats (thread = one (t,f) pair) ----
    {
        const int t = tid >> 3, f = tid & 7;
        float* row = &xc[t * IN_CH];
        // week: rows 20+t .. 24+t  -> xe index 15+t .. 19+t
        float s = 0.f, s2 = 0.f, mx = -1e30f, mn = 1e30f;
        #pragma unroll
        for (int j = 0; j < 5; ++j) {
            float v = xe[(15 + t + j) * 8 + f];
            s += v; s2 = fmaf(v, v, s2);
            mx = fmaxf(mx, v); mn = fminf(mn, v);
        }
        float mean = s * 0.2f;
        float var  = (s2 - s * s * 0.2f) * 0.25f;
        row[64 + f] = mean;
        row[72 + f] = sqrtf(fmaxf(var, 0.f));
        row[88 + f] = mx;
        row[96 + f] = mn;
        // month: rows 5+t .. 24+t -> xe index t .. t+19
        s = 0.f; s2 = 0.f; mx = -1e30f; mn = 1e30f;
        #pragma unroll
        for (int j = 0; j < 20; ++j) {
            float v = xe[(t + j) * 8 + f];
            s += v; s2 = fmaf(v, v, s2);
            mx = fmaxf(mx, v); mn = fminf(mn, v);
        }
        mean = s * 0.05f;
        var  = (s2 - s * s * 0.05f) * (1.0f / 19.0f);
        row[104 + f] = mean;
        row[112 + f] = sqrtf(fmaxf(var, 0.f));
        row[128 + f] = mx;
        row[136 + f] = mn;
    }
    __syncthreads();

    // ---- phase 3: conv channel 127 (8 lanes per output t, 18 channels each) ----
    float partial = 0.0f;
    if (tid < LIN_IN * 8) {
        const int g = tid & 7, t = tid >> 3;
        const float* xr = &xc[t * IN_CH];
        const int i0 = g * 18;
        #pragma unroll
        for (int ii = 0; ii < 18; ++ii) {
            int i = i0 + ii;
            const float* w = &ws[i * KERNEL];
            float acc = 0.f;
            #pragma unroll
            for (int k = 0; k < KERNEL; ++k)
                acc = fmaf(w[k], xr[k * IN_CH + i], acc);
            partial += acc;
        }
    }
    partial += __shfl_down_sync(0xFFFFFFFFu, partial, 4, 8);
    partial += __shfl_down_sync(0xFFFFFFFFu, partial, 2, 8);
    partial += __shfl_down_sync(0xFFFFFFFFu, partial, 1, 8);
    if ((tid & 7) == 0 && tid < LIN_IN * 8) {
        int t = tid >> 3;
        float s = partial + conv_b[127];
        s = (s >= 0.0f) ? s : 0.01f * s;   // leaky ALPHA=0.01
        atomicAdd(&red, s * lw[t]);
    }
    __syncthreads();
    if (tid == 0) out[n] = red + lin_b[0];
}

// ---------------------------------------------------------------------------
extern "C" void kernel_launch(void* const* d_in, const int* in_sizes, int n_in,
                              void* d_out, int out_size) {
    const float* x      = (const float*)d_in[0];
    const float* conv_w = (const float*)d_in[1];
    const float* conv_b = (const float*)d_in[2];
    const float* lin_w  = (const float*)d_in[3];
    const float* lin_b  = (const float*)d_in[4];
    float* out = (float*)d_out;
    const int N = in_sizes[0] / (TDIM * FDIM);   // 8000

    dim3 gg((N + 255) / 256, WINDOW);
    gather_kernel<<<gg, 256>>>(x, N);
    rank_kernel<<<NCOL, RT>>>(N);
    main_kernel<<<N, 320>>>(x, conv_w, conv_b, lin_w, lin_b, out, N);
}